// round 13
// baseline (speedup 1.0000x reference)
#include <cuda_runtime.h>
#include <cuda_bf16.h>
#include <math.h>
#include <stdint.h>

// ---------------------------------------------------------------------------
// Round 13: SINGLE-LAUNCH SM PARTITION (producer/consumer at BLOCK level).
// Grid = #SMs, 1 block/SM (full smem). Blocks [0, ngather) stream the hash
// gather into g_enc chunk-by-chunk (LTS-bound role); blocks [ngather, sms)
// run the R12 register-chained bf16x3 tensor MLP, waiting per chunk on a
// device flag (release: threadfence+atomicAdd; acquire: volatile spin +
// __ldcg enc reads). ngather = sms-128 so MLP has exactly 128 blocks =
// tiles-per-chunk. A reset prologue kernel zeroes flags for graph replays.
// ---------------------------------------------------------------------------

#define LVLS 24
#define TSZ  (1u << 19)
#define P1   2654435761u
#define P2   805459861u

#define NPTS      524288
#define TILE_PTS  256
#define NTHREADS  512
#define NCHUNKS   16

#define WOFF_L0 0              // 64 x 56 (K=48)
#define WOFF_L1 3584           // 64 x 72
#define WOFF_L2 8192           // 64 x 72
#define WOFF_L3 12800          // 72 x 72 (N 65->72)
#define WOFF_R0 17984          // 64 x 88 (K=80, staged shifted by 1)
#define WOFF_R1 23616          // 64 x 72
#define WOFF_R2 28224          //  8 x 72 (N 3->8)

#define BOFF_L0 0
#define BOFF_L1 64
#define BOFF_L2 128
#define BOFF_L3 192
#define BOFF_R0 264
#define BOFF_R1 328
#define BOFF_R2 392

#define SO_WHI  0
#define SO_WLO  57600
#define SO_BIAS 115200
#define SMEM_BYTES (SO_BIAS + 400 * 4)        // 116800

struct ResArr { float r[LVLS]; };
struct WPtrs  { const float* w[14]; };

typedef unsigned short u16;
typedef unsigned int   u32;

__device__ u32 g_enc[(size_t)NPTS * LVLS];    // [point][level] packed bf16x2
__device__ int g_done[NCHUNKS];

__device__ __forceinline__ float gelu_exact(float x) {
    return 0.5f * x * (1.0f + erff(x * 0.70710678118654752440f));
}
__device__ __forceinline__ float softplus_f(float x) {
    return fmaxf(x, 0.0f) + log1pf(expf(-fabsf(x)));
}
__device__ __forceinline__ float sigmoid_f(float x) {
    return 1.0f / (1.0f + expf(-x));
}

#define MMA_BF16(d, a0, a1, a2, a3, b0, b1)                                   \
    asm volatile(                                                             \
        "mma.sync.aligned.m16n8k16.row.col.f32.bf16.bf16.f32 "                \
        "{%0,%1,%2,%3}, {%4,%5,%6,%7}, {%8,%9}, {%0,%1,%2,%3};"               \
        : "+f"(d[0]), "+f"(d[1]), "+f"(d[2]), "+f"(d[3])                      \
        : "r"(a0), "r"(a1), "r"(a2), "r"(a3), "r"(b0), "r"(b1))

#define LDSM_X4(r0, r1, r2, r3, addr)                                         \
    asm volatile("ldmatrix.sync.aligned.m8n8.x4.shared.b16 {%0,%1,%2,%3}, [%4];" \
        : "=r"(r0), "=r"(r1), "=r"(r2), "=r"(r3) : "r"(addr))

#define LDSM_X2(r0, r1, addr)                                                 \
    asm volatile("ldmatrix.sync.aligned.m8n8.x2.shared.b16 {%0,%1}, [%2];"    \
        : "=r"(r0), "=r"(r1) : "r"(addr))

__device__ __forceinline__ void pack_split2(float v0, float v1,
                                            u32& h, u32& l) {
    u32 hh;
    asm("cvt.rn.bf16x2.f32 %0, %1, %2;" : "=r"(hh) : "f"(v1), "f"(v0));
    float f0 = __uint_as_float(hh << 16);
    float f1 = __uint_as_float(hh & 0xffff0000u);
    asm("cvt.rn.bf16x2.f32 %0, %1, %2;" : "=r"(l) : "f"(v1 - f1), "f"(v0 - f0));
    h = hh;
}

template<int KP>
__device__ __forceinline__ u32 lane_adj(int lane) {
    int row8  = lane & 7;
    int which = lane >> 3;
    int n_off = ((which & 2) << 2) + row8;
    int k_off = (which & 1) << 3;
    return (u32)((n_off * KP + k_off) * 2);
}

// 3-term layer (activation hi/lo in registers)
template<int K0, int K1, int NT, int KP, bool INIT>
__device__ __forceinline__ void run_layer_lds(const u32* __restrict__ ah,
                                              const u32* __restrict__ al,
                                              u32 shi, u32 slo,
                                              const float* __restrict__ bias,
                                              float (&acc)[NT][4], int qm)
{
    if (INIT) {
#pragma unroll
        for (int nt = 0; nt < NT; nt++) {
            float b0 = bias[nt * 8 + 2 * qm];
            float b1 = bias[nt * 8 + 2 * qm + 1];
            acc[nt][0] = b0; acc[nt][1] = b1;
            acc[nt][2] = b0; acc[nt][3] = b1;
        }
    }
#pragma unroll
    for (int kt = K0; kt < K1; kt++) {
#pragma unroll
        for (int p = 0; p < NT / 2; p++) {
            u32 off = (u32)((p * 16 * KP + kt * 16) * 2);
            u32 bh0, bh1, bh2, bh3, bl0, bl1, bl2, bl3;
            LDSM_X4(bh0, bh1, bh2, bh3, shi + off);
            LDSM_X4(bl0, bl1, bl2, bl3, slo + off);
            MMA_BF16(acc[2*p], ah[4*kt], ah[4*kt+1], ah[4*kt+2], ah[4*kt+3], bh0, bh1);
            MMA_BF16(acc[2*p], ah[4*kt], ah[4*kt+1], ah[4*kt+2], ah[4*kt+3], bl0, bl1);
            MMA_BF16(acc[2*p], al[4*kt], al[4*kt+1], al[4*kt+2], al[4*kt+3], bh0, bh1);
            MMA_BF16(acc[2*p+1], ah[4*kt], ah[4*kt+1], ah[4*kt+2], ah[4*kt+3], bh2, bh3);
            MMA_BF16(acc[2*p+1], ah[4*kt], ah[4*kt+1], ah[4*kt+2], ah[4*kt+3], bl2, bl3);
            MMA_BF16(acc[2*p+1], al[4*kt], al[4*kt+1], al[4*kt+2], al[4*kt+3], bh2, bh3);
        }
        if (NT & 1) {
            u32 off = (u32)(((NT - 1) * 8 * KP + kt * 16) * 2);
            u32 bh0, bh1, bl0, bl1;
            LDSM_X2(bh0, bh1, shi + off);
            LDSM_X2(bl0, bl1, slo + off);
            MMA_BF16(acc[NT-1], ah[4*kt], ah[4*kt+1], ah[4*kt+2], ah[4*kt+3], bh0, bh1);
            MMA_BF16(acc[NT-1], ah[4*kt], ah[4*kt+1], ah[4*kt+2], ah[4*kt+3], bl0, bl1);
            MMA_BF16(acc[NT-1], al[4*kt], al[4*kt+1], al[4*kt+2], al[4*kt+3], bh0, bh1);
        }
    }
}

// L0: A is bf16-only (enc), 2-term
template<int NT, int KP>
__device__ __forceinline__ void run_layer_l0(const u32* __restrict__ ah,
                                             u32 shi, u32 slo,
                                             const float* __restrict__ bias,
                                             float (&acc)[NT][4], int qm)
{
#pragma unroll
    for (int nt = 0; nt < NT; nt++) {
        float b0 = bias[nt * 8 + 2 * qm];
        float b1 = bias[nt * 8 + 2 * qm + 1];
        acc[nt][0] = b0; acc[nt][1] = b1;
        acc[nt][2] = b0; acc[nt][3] = b1;
    }
#pragma unroll
    for (int kt = 0; kt < 3; kt++) {
#pragma unroll
        for (int p = 0; p < NT / 2; p++) {
            u32 off = (u32)((p * 16 * KP + kt * 16) * 2);
            u32 bh0, bh1, bh2, bh3, bl0, bl1, bl2, bl3;
            LDSM_X4(bh0, bh1, bh2, bh3, shi + off);
            LDSM_X4(bl0, bl1, bl2, bl3, slo + off);
            MMA_BF16(acc[2*p], ah[4*kt], ah[4*kt+1], ah[4*kt+2], ah[4*kt+3], bh0, bh1);
            MMA_BF16(acc[2*p], ah[4*kt], ah[4*kt+1], ah[4*kt+2], ah[4*kt+3], bl0, bl1);
            MMA_BF16(acc[2*p+1], ah[4*kt], ah[4*kt+1], ah[4*kt+2], ah[4*kt+3], bh2, bh3);
            MMA_BF16(acc[2*p+1], ah[4*kt], ah[4*kt+1], ah[4*kt+2], ah[4*kt+3], bl2, bl3);
        }
    }
}

template<int KTN>
__device__ __forceinline__ void frags_gelu(const float (*acc)[4],
                                           u32* ah, u32* al)
{
#pragma unroll
    for (int kt = 0; kt < KTN; kt++) {
        pack_split2(gelu_exact(acc[2*kt][0]),   gelu_exact(acc[2*kt][1]),
                    ah[4*kt+0], al[4*kt+0]);
        pack_split2(gelu_exact(acc[2*kt][2]),   gelu_exact(acc[2*kt][3]),
                    ah[4*kt+1], al[4*kt+1]);
        pack_split2(gelu_exact(acc[2*kt+1][0]), gelu_exact(acc[2*kt+1][1]),
                    ah[4*kt+2], al[4*kt+2]);
        pack_split2(gelu_exact(acc[2*kt+1][2]), gelu_exact(acc[2*kt+1][3]),
                    ah[4*kt+3], al[4*kt+3]);
    }
}

// ---- staging ----
__device__ void stage_w(const float* __restrict__ g, u16* hi, u16* lo,
                        int realK, int realN, int K, int NPAD, int KP, int tid)
{
    for (int idx = tid; idx < NPAD * K; idx += NTHREADS) {
        int nn = idx / K, kk = idx % K;
        float v = (kk < realK && nn < realN) ? g[kk * realN + nn] : 0.0f;
        u32 h, l;
        pack_split2(v, 0.0f, h, l);
        hi[nn * KP + kk] = (u16)(h & 0xffff);
        lo[nn * KP + kk] = (u16)(l & 0xffff);
    }
}
__device__ void stage_w_shift(const float* __restrict__ g, u16* hi, u16* lo,
                              int tid)
{
    const int K = 80, KP = 88;
    for (int idx = tid; idx < 64 * K; idx += NTHREADS) {
        int nn = idx / K, kk = idx % K;
        float v = (kk >= 1 && kk <= 73) ? g[(kk - 1) * 64 + nn] : 0.0f;
        u32 h, l;
        pack_split2(v, 0.0f, h, l);
        hi[nn * KP + kk] = (u16)(h & 0xffff);
        lo[nn * KP + kk] = (u16)(l & 0xffff);
    }
}
__device__ void stage_b(const float* __restrict__ g, float* dst,
                        int realN, int NPAD, int tid)
{
    for (int i = tid; i < NPAD; i += NTHREADS)
        dst[i] = (i < realN) ? g[i] : 0.0f;
}

// ---- prologue: zero chunk flags (graph-replay safe) ----
__global__ void reset_kernel()
{
    if (threadIdx.x < NCHUNKS) g_done[threadIdx.x] = 0;
}

__global__ void __launch_bounds__(NTHREADS, 1)
fused_kernel(const float* __restrict__ pts,
             const float* __restrict__ dirs,
             const float* __restrict__ table,
             WPtrs prm, ResArr res,
             float* __restrict__ out, int n, int ngather)
{
    extern __shared__ char smem[];
    const int tid  = threadIdx.x;
    const int chunk_pts = n / NCHUNKS;

    // ======================= GATHER ROLE =======================
    if ((int)blockIdx.x < ngather) {
        const int gthreads = ngather * NTHREADS;
        const int gtid = blockIdx.x * NTHREADS + tid;
        for (int c = 0; c < NCHUNKS; c++) {
            const int pbase = c * chunk_pts;
            const int units = chunk_pts * LVLS;
            for (int u = gtid; u < units; u += gthreads) {
                int p = pbase + u / LVLS;
                int l = u - (u / LVLS) * LVLS;

                float x0 = (pts[p * 3 + 0] + 1.0f) * 0.5f;
                float y0 = (pts[p * 3 + 1] + 1.0f) * 0.5f;
                float z0 = (pts[p * 3 + 2] + 1.0f) * 0.5f;

                float rl = res.r[l];
                float posx = x0 * rl, posy = y0 * rl, posz = z0 * rl;
                float fx = floorf(posx), fy = floorf(posy), fz = floorf(posz);
                float wx = posx - fx, wy = posy - fy, wz = posz - fz;
                unsigned ux = (unsigned)fx, uy = (unsigned)fy,
                         uz = (unsigned)fz;
                unsigned hX[2] = {ux, ux + 1u};
                unsigned hY[2] = {uy * P1, (uy + 1u) * P1};
                unsigned hZ[2] = {uz * P2, (uz + 1u) * P2};
                float wX[2] = {1.0f - wx, wx};
                float wY[2] = {1.0f - wy, wy};
                float wZ[2] = {1.0f - wz, wz};
                const float2* tb = (const float2*)table + (size_t)l * TSZ;

                float2 f[8]; float wt[8];
#pragma unroll
                for (int cc = 0; cc < 8; cc++) {
                    int bx = (cc >> 2) & 1, by = (cc >> 1) & 1, bz = cc & 1;
                    unsigned idx = (hX[bx] ^ hY[by] ^ hZ[bz]) & (TSZ - 1u);
                    f[cc]  = __ldg(tb + idx);
                    wt[cc] = wX[bx] * wY[by] * wZ[bz];
                }
                float a0 = 0.0f, a1 = 0.0f;
#pragma unroll
                for (int cc = 0; cc < 8; cc++) {
                    a0 = fmaf(f[cc].x, wt[cc], a0);
                    a1 = fmaf(f[cc].y, wt[cc], a1);
                }
                u32 h;
                asm("cvt.rn.bf16x2.f32 %0, %1, %2;" : "=r"(h)
                    : "f"(a1), "f"(a0));
                g_enc[(size_t)p * LVLS + l] = h;
            }
            __threadfence();     // release enc stores to L2
            __syncthreads();     // whole block done with chunk c
            if (tid == 0) atomicAdd(&g_done[c], 1);
        }
        return;
    }

    // ======================= MLP ROLE =======================
    u16*   whi  = (u16*)(smem + SO_WHI);
    u16*   wlo  = (u16*)(smem + SO_WLO);
    float* bias = (float*)(smem + SO_BIAS);

    const int warp = tid >> 5;
    const int lane = tid & 31;
    const int qr = lane >> 2, qm = lane & 3;
    const int rg = warp;

    stage_w(prm.w[0],  whi + WOFF_L0, wlo + WOFF_L0, 48, 64, 48, 64, 56, tid);
    stage_w(prm.w[2],  whi + WOFF_L1, wlo + WOFF_L1, 64, 64, 64, 64, 72, tid);
    stage_w(prm.w[4],  whi + WOFF_L2, wlo + WOFF_L2, 64, 64, 64, 64, 72, tid);
    stage_w(prm.w[6],  whi + WOFF_L3, wlo + WOFF_L3, 64, 65, 64, 72, 72, tid);
    stage_w_shift(prm.w[8], whi + WOFF_R0, wlo + WOFF_R0, tid);
    stage_w(prm.w[10], whi + WOFF_R1, wlo + WOFF_R1, 64, 64, 64, 64, 72, tid);
    stage_w(prm.w[12], whi + WOFF_R2, wlo + WOFF_R2, 64,  3, 64,  8, 72, tid);
    stage_b(prm.w[1],  bias + BOFF_L0, 64, 64, tid);
    stage_b(prm.w[3],  bias + BOFF_L1, 64, 64, tid);
    stage_b(prm.w[5],  bias + BOFF_L2, 64, 64, tid);
    stage_b(prm.w[7],  bias + BOFF_L3, 65, 72, tid);
    stage_b(prm.w[9],  bias + BOFF_R0, 64, 64, tid);
    stage_b(prm.w[11], bias + BOFF_R1, 64, 64, tid);
    stage_b(prm.w[13], bias + BOFF_R2,  3,  8, tid);
    __syncthreads();

    const u32 whi_s = (u32)__cvta_generic_to_shared(whi);
    const u32 wlo_s = (u32)__cvta_generic_to_shared(wlo);
    const u32 adj56 = lane_adj<56>(lane);
    const u32 adj72 = lane_adj<72>(lane);
    const u32 adj88 = lane_adj<88>(lane);
    const u32 sL0h = whi_s + WOFF_L0*2 + adj56, sL0l = wlo_s + WOFF_L0*2 + adj56;
    const u32 sL1h = whi_s + WOFF_L1*2 + adj72, sL1l = wlo_s + WOFF_L1*2 + adj72;
    const u32 sL2h = whi_s + WOFF_L2*2 + adj72, sL2l = wlo_s + WOFF_L2*2 + adj72;
    const u32 sL3h = whi_s + WOFF_L3*2 + adj72, sL3l = wlo_s + WOFF_L3*2 + adj72;
    const u32 sR0h = whi_s + WOFF_R0*2 + adj88, sR0l = wlo_s + WOFF_R0*2 + adj88;
    const u32 sR1h = whi_s + WOFF_R1*2 + adj72, sR1l = wlo_s + WOFF_R1*2 + adj72;
    const u32 sR2h = whi_s + WOFF_R2*2 + adj72, sR2l = wlo_s + WOFF_R2*2 + adj72;

    const int mbid = blockIdx.x - ngather;
    const int nmlp = gridDim.x - ngather;
    const int tpc  = chunk_pts / TILE_PTS;   // tiles per chunk

    for (int c = 0; c < NCHUNKS; c++) {
        // acquire: wait for all gather blocks to finish chunk c
        if (tid == 0) {
            volatile int* dp = &g_done[c];
            while (*dp < ngather) { }
        }
        __syncthreads();
        __threadfence();

        for (int tile = c * tpc + mbid; tile < (c + 1) * tpc; tile += nmlp) {
            const int base = tile * TILE_PTS;

            u32 ah[20], al[20];
            float dxA, dyA, dzA, dxB, dyB, dzB;
            {
                int pt0 = base + rg * 16 + qr;
                int pt1 = pt0 + 8;
                const u32* e0 = g_enc + (size_t)pt0 * LVLS;
                const u32* e1 = g_enc + (size_t)pt1 * LVLS;
#pragma unroll
                for (int kt = 0; kt < 3; kt++) {
                    ah[4*kt+0] = __ldcg(e0 + qm + 8 * kt);
                    ah[4*kt+1] = __ldcg(e1 + qm + 8 * kt);
                    ah[4*kt+2] = __ldcg(e0 + qm + 8 * kt + 4);
                    ah[4*kt+3] = __ldcg(e1 + qm + 8 * kt + 4);
                }
                dxA = __ldg(dirs + pt0 * 3 + 0);
                dyA = __ldg(dirs + pt0 * 3 + 1);
                dzA = __ldg(dirs + pt0 * 3 + 2);
                dxB = __ldg(dirs + pt1 * 3 + 0);
                dyB = __ldg(dirs + pt1 * 3 + 1);
                dzB = __ldg(dirs + pt1 * 3 + 2);
            }

            float acc[8][4];
            run_layer_l0<8, 56>(ah, sL0h, sL0l, bias + BOFF_L0, acc, qm);

            frags_gelu<4>(acc, ah, al);
            run_layer_lds<0, 4, 8, 72, true>(ah, al, sL1h, sL1l,
                                             bias + BOFF_L1, acc, qm);
            frags_gelu<4>(acc, ah, al);
            run_layer_lds<0, 4, 8, 72, true>(ah, al, sL2h, sL2l,
                                             bias + BOFF_L2, acc, qm);
            frags_gelu<4>(acc, ah, al);
            float acc9[9][4];
            run_layer_lds<0, 4, 9, 72, true>(ah, al, sL3h, sL3l,
                                             bias + BOFF_L3, acc9, qm);

            if (qm == 0) {
                int pA = base + rg * 16 + qr;
                out[(size_t)3 * n + pA]     = softplus_f(acc9[0][0]);
                out[(size_t)3 * n + pA + 8] = softplus_f(acc9[0][2]);
            }

            float shA[9], shB[9];
            shA[0] = 0.28209479177387814f;
            shA[1] = -0.48860251190291987f * dyA;
            shA[2] =  0.48860251190291987f * dzA;
            shA[3] = -0.48860251190291987f * dxA;
            shA[4] =  1.0925484305920792f  * dxA * dyA;
            shA[5] = -1.0925484305920792f  * dyA * dzA;
            shA[6] =  0.31539156525252005f * (3.0f * dzA * dzA - 1.0f);
            shA[7] = -1.0925484305920792f  * dxA * dzA;
            shA[8] =  0.5462742152960396f  * (dxA * dxA - dyA * dyA);
            shB[0] = 0.28209479177387814f;
            shB[1] = -0.48860251190291987f * dyB;
            shB[2] =  0.48860251190291987f * dzB;
            shB[3] = -0.48860251190291987f * dxB;
            shB[4] =  1.0925484305920792f  * dxB * dyB;
            shB[5] = -1.0925484305920792f  * dyB * dzB;
            shB[6] =  0.31539156525252005f * (3.0f * dzB * dzB - 1.0f);
            shB[7] = -1.0925484305920792f  * dxB * dzB;
            shB[8] =  0.5462742152960396f  * (dxB * dxB - dyB * dyB);

            frags_gelu<4>(acc9, ah, al);
            {
                float e64A = gelu_exact(acc9[8][0]);
                float e64B = gelu_exact(acc9[8][2]);
                float v0A, v1A, v2A, v3A, v0B, v1B, v2B, v3B;
                if (qm == 0) {
                    v0A = e64A;   v1A = shA[0]; v2A = shA[7]; v3A = shA[8];
                    v0B = e64B;   v1B = shB[0]; v2B = shB[7]; v3B = shB[8];
                } else if (qm == 1) {
                    v0A = shA[1]; v1A = shA[2]; v2A = 0.0f;   v3A = 0.0f;
                    v0B = shB[1]; v1B = shB[2]; v2B = 0.0f;   v3B = 0.0f;
                } else if (qm == 2) {
                    v0A = shA[3]; v1A = shA[4]; v2A = 0.0f;   v3A = 0.0f;
                    v0B = shB[3]; v1B = shB[4]; v2B = 0.0f;   v3B = 0.0f;
                } else {
                    v0A = shA[5]; v1A = shA[6]; v2A = 0.0f;   v3A = 0.0f;
                    v0B = shB[5]; v1B = shB[6]; v2B = 0.0f;   v3B = 0.0f;
                }
                pack_split2(v0A, v1A, ah[16], al[16]);
                pack_split2(v0B, v1B, ah[17], al[17]);
                pack_split2(v2A, v3A, ah[18], al[18]);
                pack_split2(v2B, v3B, ah[19], al[19]);
            }

            run_layer_lds<0, 5, 8, 88, true>(ah, al, sR0h, sR0l,
                                             bias + BOFF_R0, acc, qm);
            frags_gelu<4>(acc, ah, al);
            run_layer_lds<0, 4, 8, 72, true>(ah, al, sR1h, sR1l,
                                             bias + BOFF_R1, acc, qm);
            frags_gelu<4>(acc, ah, al);
            {
                float acc1[1][4];
                run_layer_lds<0, 4, 1, 72, true>(ah, al, sR2h, sR2l,
                                                 bias + BOFF_R2, acc1, qm);
                int pt0 = base + rg * 16 + qr;
                int pt1 = pt0 + 8;
                if (qm == 0) {
                    out[pt0 * 3 + 0] = sigmoid_f(acc1[0][0]);
                    out[pt0 * 3 + 1] = sigmoid_f(acc1[0][1]);
                    out[pt1 * 3 + 0] = sigmoid_f(acc1[0][2]);
                    out[pt1 * 3 + 1] = sigmoid_f(acc1[0][3]);
                } else if (qm == 1) {
                    out[pt0 * 3 + 2] = sigmoid_f(acc1[0][0]);
                    out[pt1 * 3 + 2] = sigmoid_f(acc1[0][2]);
                }
            }
        }
    }
}

extern "C" void kernel_launch(void* const* d_in, const int* in_sizes, int n_in,
                              void* d_out, int out_size)
{
    const float* pts   = (const float*)d_in[0];
    const float* dirs  = (const float*)d_in[1];
    const float* table = (const float*)d_in[2];

    WPtrs prm;
    for (int a = 0; a < 14; a++) prm.w[a] = (const float*)d_in[3 + a];

    int n = in_sizes[0] / 3;

    ResArr res;
    double b = exp((log(2048.0) - log(16.0)) / 23.0);
    for (int l = 0; l < LVLS; l++)
        res.r[l] = (float)floor(16.0 * pow(b, (double)l));

    int dev = 0, sms = 148;
    cudaGetDevice(&dev);
    cudaDeviceGetAttribute(&sms, cudaDevAttrMultiProcessorCount, dev);

    // MLP gets exactly tiles-per-chunk (=128) blocks; rest gather.
    int tpc = (n / NCHUNKS) / TILE_PTS;      // 128
    int ngather = sms - tpc;                 // 20 on 148 SMs, 24 on 152
    if (ngather < 8) ngather = 8;

    reset_kernel<<<1, 32>>>();

    cudaFuncSetAttribute(fused_kernel,
                         cudaFuncAttributeMaxDynamicSharedMemorySize,
                         SMEM_BYTES);
    fused_kernel<<<sms, NTHREADS, SMEM_BYTES>>>(
        pts, dirs, table, prm, res, (float*)d_out, n, ngather);
}

// round 14
// speedup vs baseline: 1.0862x; 1.0862x over previous
#include <cuda_runtime.h>
#include <cuda_bf16.h>
#include <math.h>
#include <stdint.h>

// ---------------------------------------------------------------------------
// Round 14: SM partition (R13) with the two defects fixed:
//  (1) spin-wait uses __nanosleep backoff (no LTS-slice hammering)
//  (2) gather role runs a DEPTH-2 unit pipeline (16 outstanding loads/thread)
//      so ~24 gather blocks saturate LTS while 128 MLP blocks run the
//      register-chained bf16x3 tensor pipeline on their own SMs.
// Gather chunk c releases via threadfence+atomicAdd; MLP acquires via
// backoff-poll, reads enc with __ldcg. reset prologue for graph replays.
// ---------------------------------------------------------------------------

#define LVLS 24
#define TSZ  (1u << 19)
#define P1   2654435761u
#define P2   805459861u

#define NPTS      524288
#define TILE_PTS  256
#define NTHREADS  512
#define NCHUNKS   16

#define WOFF_L0 0
#define WOFF_L1 3584
#define WOFF_L2 8192
#define WOFF_L3 12800
#define WOFF_R0 17984
#define WOFF_R1 23616
#define WOFF_R2 28224

#define BOFF_L0 0
#define BOFF_L1 64
#define BOFF_L2 128
#define BOFF_L3 192
#define BOFF_R0 264
#define BOFF_R1 328
#define BOFF_R2 392

#define SO_WHI  0
#define SO_WLO  57600
#define SO_BIAS 115200
#define SMEM_BYTES (SO_BIAS + 400 * 4)

struct ResArr { float r[LVLS]; };
struct WPtrs  { const float* w[14]; };

typedef unsigned short u16;
typedef unsigned int   u32;

__device__ u32 g_enc[(size_t)NPTS * LVLS];
__device__ int g_done[NCHUNKS];

__device__ __forceinline__ float gelu_exact(float x) {
    return 0.5f * x * (1.0f + erff(x * 0.70710678118654752440f));
}
__device__ __forceinline__ float softplus_f(float x) {
    return fmaxf(x, 0.0f) + log1pf(expf(-fabsf(x)));
}
__device__ __forceinline__ float sigmoid_f(float x) {
    return 1.0f / (1.0f + expf(-x));
}

#define MMA_BF16(d, a0, a1, a2, a3, b0, b1)                                   \
    asm volatile(                                                             \
        "mma.sync.aligned.m16n8k16.row.col.f32.bf16.bf16.f32 "                \
        "{%0,%1,%2,%3}, {%4,%5,%6,%7}, {%8,%9}, {%0,%1,%2,%3};"               \
        : "+f"(d[0]), "+f"(d[1]), "+f"(d[2]), "+f"(d[3])                      \
        : "r"(a0), "r"(a1), "r"(a2), "r"(a3), "r"(b0), "r"(b1))

#define LDSM_X4(r0, r1, r2, r3, addr)                                         \
    asm volatile("ldmatrix.sync.aligned.m8n8.x4.shared.b16 {%0,%1,%2,%3}, [%4];" \
        : "=r"(r0), "=r"(r1), "=r"(r2), "=r"(r3) : "r"(addr))

#define LDSM_X2(r0, r1, addr)                                                 \
    asm volatile("ldmatrix.sync.aligned.m8n8.x2.shared.b16 {%0,%1}, [%2];"    \
        : "=r"(r0), "=r"(r1) : "r"(addr))

__device__ __forceinline__ void pack_split2(float v0, float v1,
                                            u32& h, u32& l) {
    u32 hh;
    asm("cvt.rn.bf16x2.f32 %0, %1, %2;" : "=r"(hh) : "f"(v1), "f"(v0));
    float f0 = __uint_as_float(hh << 16);
    float f1 = __uint_as_float(hh & 0xffff0000u);
    asm("cvt.rn.bf16x2.f32 %0, %1, %2;" : "=r"(l) : "f"(v1 - f1), "f"(v0 - f0));
    h = hh;
}

template<int KP>
__device__ __forceinline__ u32 lane_adj(int lane) {
    int row8  = lane & 7;
    int which = lane >> 3;
    int n_off = ((which & 2) << 2) + row8;
    int k_off = (which & 1) << 3;
    return (u32)((n_off * KP + k_off) * 2);
}

template<int K0, int K1, int NT, int KP, bool INIT>
__device__ __forceinline__ void run_layer_lds(const u32* __restrict__ ah,
                                              const u32* __restrict__ al,
                                              u32 shi, u32 slo,
                                              const float* __restrict__ bias,
                                              float (&acc)[NT][4], int qm)
{
    if (INIT) {
#pragma unroll
        for (int nt = 0; nt < NT; nt++) {
            float b0 = bias[nt * 8 + 2 * qm];
            float b1 = bias[nt * 8 + 2 * qm + 1];
            acc[nt][0] = b0; acc[nt][1] = b1;
            acc[nt][2] = b0; acc[nt][3] = b1;
        }
    }
#pragma unroll
    for (int kt = K0; kt < K1; kt++) {
#pragma unroll
        for (int p = 0; p < NT / 2; p++) {
            u32 off = (u32)((p * 16 * KP + kt * 16) * 2);
            u32 bh0, bh1, bh2, bh3, bl0, bl1, bl2, bl3;
            LDSM_X4(bh0, bh1, bh2, bh3, shi + off);
            LDSM_X4(bl0, bl1, bl2, bl3, slo + off);
            MMA_BF16(acc[2*p], ah[4*kt], ah[4*kt+1], ah[4*kt+2], ah[4*kt+3], bh0, bh1);
            MMA_BF16(acc[2*p], ah[4*kt], ah[4*kt+1], ah[4*kt+2], ah[4*kt+3], bl0, bl1);
            MMA_BF16(acc[2*p], al[4*kt], al[4*kt+1], al[4*kt+2], al[4*kt+3], bh0, bh1);
            MMA_BF16(acc[2*p+1], ah[4*kt], ah[4*kt+1], ah[4*kt+2], ah[4*kt+3], bh2, bh3);
            MMA_BF16(acc[2*p+1], ah[4*kt], ah[4*kt+1], ah[4*kt+2], ah[4*kt+3], bl2, bl3);
            MMA_BF16(acc[2*p+1], al[4*kt], al[4*kt+1], al[4*kt+2], al[4*kt+3], bh2, bh3);
        }
        if (NT & 1) {
            u32 off = (u32)(((NT - 1) * 8 * KP + kt * 16) * 2);
            u32 bh0, bh1, bl0, bl1;
            LDSM_X2(bh0, bh1, shi + off);
            LDSM_X2(bl0, bl1, slo + off);
            MMA_BF16(acc[NT-1], ah[4*kt], ah[4*kt+1], ah[4*kt+2], ah[4*kt+3], bh0, bh1);
            MMA_BF16(acc[NT-1], ah[4*kt], ah[4*kt+1], ah[4*kt+2], ah[4*kt+3], bl0, bl1);
            MMA_BF16(acc[NT-1], al[4*kt], al[4*kt+1], al[4*kt+2], al[4*kt+3], bh0, bh1);
        }
    }
}

template<int NT, int KP>
__device__ __forceinline__ void run_layer_l0(const u32* __restrict__ ah,
                                             u32 shi, u32 slo,
                                             const float* __restrict__ bias,
                                             float (&acc)[NT][4], int qm)
{
#pragma unroll
    for (int nt = 0; nt < NT; nt++) {
        float b0 = bias[nt * 8 + 2 * qm];
        float b1 = bias[nt * 8 + 2 * qm + 1];
        acc[nt][0] = b0; acc[nt][1] = b1;
        acc[nt][2] = b0; acc[nt][3] = b1;
    }
#pragma unroll
    for (int kt = 0; kt < 3; kt++) {
#pragma unroll
        for (int p = 0; p < NT / 2; p++) {
            u32 off = (u32)((p * 16 * KP + kt * 16) * 2);
            u32 bh0, bh1, bh2, bh3, bl0, bl1, bl2, bl3;
            LDSM_X4(bh0, bh1, bh2, bh3, shi + off);
            LDSM_X4(bl0, bl1, bl2, bl3, slo + off);
            MMA_BF16(acc[2*p], ah[4*kt], ah[4*kt+1], ah[4*kt+2], ah[4*kt+3], bh0, bh1);
            MMA_BF16(acc[2*p], ah[4*kt], ah[4*kt+1], ah[4*kt+2], ah[4*kt+3], bl0, bl1);
            MMA_BF16(acc[2*p+1], ah[4*kt], ah[4*kt+1], ah[4*kt+2], ah[4*kt+3], bh2, bh3);
            MMA_BF16(acc[2*p+1], ah[4*kt], ah[4*kt+1], ah[4*kt+2], ah[4*kt+3], bl2, bl3);
        }
    }
}

template<int KTN>
__device__ __forceinline__ void frags_gelu(const float (*acc)[4],
                                           u32* ah, u32* al)
{
#pragma unroll
    for (int kt = 0; kt < KTN; kt++) {
        pack_split2(gelu_exact(acc[2*kt][0]),   gelu_exact(acc[2*kt][1]),
                    ah[4*kt+0], al[4*kt+0]);
        pack_split2(gelu_exact(acc[2*kt][2]),   gelu_exact(acc[2*kt][3]),
                    ah[4*kt+1], al[4*kt+1]);
        pack_split2(gelu_exact(acc[2*kt+1][0]), gelu_exact(acc[2*kt+1][1]),
                    ah[4*kt+2], al[4*kt+2]);
        pack_split2(gelu_exact(acc[2*kt+1][2]), gelu_exact(acc[2*kt+1][3]),
                    ah[4*kt+3], al[4*kt+3]);
    }
}

// ---- gather pipeline state ----
struct GS {
    float2 f[8];
    float wx, wy, wz;
    int p, l;
};

__device__ __forceinline__ void g_issue(const float* __restrict__ pts,
                                        const float* __restrict__ table,
                                        const ResArr& res, int pbase,
                                        int chunk_pts, int u, GS& s)
{
    int l = u / chunk_pts;
    int p = pbase + (u - l * chunk_pts);
    s.p = p; s.l = l;
    float x0 = (pts[p * 3 + 0] + 1.0f) * 0.5f;
    float y0 = (pts[p * 3 + 1] + 1.0f) * 0.5f;
    float z0 = (pts[p * 3 + 2] + 1.0f) * 0.5f;
    float rl = res.r[l];
    float posx = x0 * rl, posy = y0 * rl, posz = z0 * rl;
    float fx = floorf(posx), fy = floorf(posy), fz = floorf(posz);
    s.wx = posx - fx; s.wy = posy - fy; s.wz = posz - fz;
    unsigned ux = (unsigned)fx, uy = (unsigned)fy, uz = (unsigned)fz;
    unsigned hX[2] = {ux, ux + 1u};
    unsigned hY[2] = {uy * P1, (uy + 1u) * P1};
    unsigned hZ[2] = {uz * P2, (uz + 1u) * P2};
    const float2* tb = (const float2*)table + (size_t)l * TSZ;
#pragma unroll
    for (int c = 0; c < 8; c++) {
        int bx = (c >> 2) & 1, by = (c >> 1) & 1, bz = c & 1;
        unsigned idx = (hX[bx] ^ hY[by] ^ hZ[bz]) & (TSZ - 1u);
        s.f[c] = __ldg(tb + idx);
    }
}

__device__ __forceinline__ void g_consume(GS& s)
{
    float wX[2] = {1.0f - s.wx, s.wx};
    float wY[2] = {1.0f - s.wy, s.wy};
    float wZ[2] = {1.0f - s.wz, s.wz};
    float a0 = 0.0f, a1 = 0.0f;
#pragma unroll
    for (int c = 0; c < 8; c++) {
        int bx = (c >> 2) & 1, by = (c >> 1) & 1, bz = c & 1;
        float wt = wX[bx] * wY[by] * wZ[bz];
        a0 = fmaf(s.f[c].x, wt, a0);
        a1 = fmaf(s.f[c].y, wt, a1);
    }
    u32 h;
    asm("cvt.rn.bf16x2.f32 %0, %1, %2;" : "=r"(h) : "f"(a1), "f"(a0));
    g_enc[(size_t)s.p * LVLS + s.l] = h;
}

// ---- staging ----
__device__ void stage_w(const float* __restrict__ g, u16* hi, u16* lo,
                        int realK, int realN, int K, int NPAD, int KP, int tid)
{
    for (int idx = tid; idx < NPAD * K; idx += NTHREADS) {
        int nn = idx / K, kk = idx % K;
        float v = (kk < realK && nn < realN) ? g[kk * realN + nn] : 0.0f;
        u32 h, l;
        pack_split2(v, 0.0f, h, l);
        hi[nn * KP + kk] = (u16)(h & 0xffff);
        lo[nn * KP + kk] = (u16)(l & 0xffff);
    }
}
__device__ void stage_w_shift(const float* __restrict__ g, u16* hi, u16* lo,
                              int tid)
{
    const int K = 80, KP = 88;
    for (int idx = tid; idx < 64 * K; idx += NTHREADS) {
        int nn = idx / K, kk = idx % K;
        float v = (kk >= 1 && kk <= 73) ? g[(kk - 1) * 64 + nn] : 0.0f;
        u32 h, l;
        pack_split2(v, 0.0f, h, l);
        hi[nn * KP + kk] = (u16)(h & 0xffff);
        lo[nn * KP + kk] = (u16)(l & 0xffff);
    }
}
__device__ void stage_b(const float* __restrict__ g, float* dst,
                        int realN, int NPAD, int tid)
{
    for (int i = tid; i < NPAD; i += NTHREADS)
        dst[i] = (i < realN) ? g[i] : 0.0f;
}

__global__ void reset_kernel()
{
    if (threadIdx.x < NCHUNKS) g_done[threadIdx.x] = 0;
}

__global__ void __launch_bounds__(NTHREADS, 1)
fused_kernel(const float* __restrict__ pts,
             const float* __restrict__ dirs,
             const float* __restrict__ table,
             WPtrs prm, ResArr res,
             float* __restrict__ out, int n, int ngather)
{
    extern __shared__ char smem[];
    const int tid = threadIdx.x;
    const int chunk_pts = n / NCHUNKS;

    // ======================= GATHER ROLE =======================
    if ((int)blockIdx.x < ngather) {
        const int gthreads = ngather * NTHREADS;
        const int gtid = blockIdx.x * NTHREADS + tid;
        for (int c = 0; c < NCHUNKS; c++) {
            const int pbase = c * chunk_pts;
            const int units = chunk_pts * LVLS;
            GS A, B;
            int u = gtid;
            if (u < units) {
                g_issue(pts, table, res, pbase, chunk_pts, u, A);
                int u1 = u + gthreads;
                if (u1 < units)
                    g_issue(pts, table, res, pbase, chunk_pts, u1, B);
                while (true) {
                    g_consume(A);
                    {
                        int u2 = u + 2 * gthreads;
                        if (u2 < units)
                            g_issue(pts, table, res, pbase, chunk_pts, u2, A);
                    }
                    u += gthreads;
                    if (u >= units) break;
                    g_consume(B);
                    {
                        int u2 = u + 2 * gthreads;
                        if (u2 < units)
                            g_issue(pts, table, res, pbase, chunk_pts, u2, B);
                    }
                    u += gthreads;
                    if (u >= units) break;
                }
            }
            __threadfence();     // release enc stores
            __syncthreads();
            if (tid == 0) atomicAdd(&g_done[c], 1);
        }
        return;
    }

    // ======================= MLP ROLE =======================
    u16*   whi  = (u16*)(smem + SO_WHI);
    u16*   wlo  = (u16*)(smem + SO_WLO);
    float* bias = (float*)(smem + SO_BIAS);

    const int warp = tid >> 5;
    const int lane = tid & 31;
    const int qr = lane >> 2, qm = lane & 3;
    const int rg = warp;

    stage_w(prm.w[0],  whi + WOFF_L0, wlo + WOFF_L0, 48, 64, 48, 64, 56, tid);
    stage_w(prm.w[2],  whi + WOFF_L1, wlo + WOFF_L1, 64, 64, 64, 64, 72, tid);
    stage_w(prm.w[4],  whi + WOFF_L2, wlo + WOFF_L2, 64, 64, 64, 64, 72, tid);
    stage_w(prm.w[6],  whi + WOFF_L3, wlo + WOFF_L3, 64, 65, 64, 72, 72, tid);
    stage_w_shift(prm.w[8], whi + WOFF_R0, wlo + WOFF_R0, tid);
    stage_w(prm.w[10], whi + WOFF_R1, wlo + WOFF_R1, 64, 64, 64, 64, 72, tid);
    stage_w(prm.w[12], whi + WOFF_R2, wlo + WOFF_R2, 64,  3, 64,  8, 72, tid);
    stage_b(prm.w[1],  bias + BOFF_L0, 64, 64, tid);
    stage_b(prm.w[3],  bias + BOFF_L1, 64, 64, tid);
    stage_b(prm.w[5],  bias + BOFF_L2, 64, 64, tid);
    stage_b(prm.w[7],  bias + BOFF_L3, 65, 72, tid);
    stage_b(prm.w[9],  bias + BOFF_R0, 64, 64, tid);
    stage_b(prm.w[11], bias + BOFF_R1, 64, 64, tid);
    stage_b(prm.w[13], bias + BOFF_R2,  3,  8, tid);
    __syncthreads();

    const u32 whi_s = (u32)__cvta_generic_to_shared(whi);
    const u32 wlo_s = (u32)__cvta_generic_to_shared(wlo);
    const u32 adj56 = lane_adj<56>(lane);
    const u32 adj72 = lane_adj<72>(lane);
    const u32 adj88 = lane_adj<88>(lane);
    const u32 sL0h = whi_s + WOFF_L0*2 + adj56, sL0l = wlo_s + WOFF_L0*2 + adj56;
    const u32 sL1h = whi_s + WOFF_L1*2 + adj72, sL1l = wlo_s + WOFF_L1*2 + adj72;
    const u32 sL2h = whi_s + WOFF_L2*2 + adj72, sL2l = wlo_s + WOFF_L2*2 + adj72;
    const u32 sL3h = whi_s + WOFF_L3*2 + adj72, sL3l = wlo_s + WOFF_L3*2 + adj72;
    const u32 sR0h = whi_s + WOFF_R0*2 + adj88, sR0l = wlo_s + WOFF_R0*2 + adj88;
    const u32 sR1h = whi_s + WOFF_R1*2 + adj72, sR1l = wlo_s + WOFF_R1*2 + adj72;
    const u32 sR2h = whi_s + WOFF_R2*2 + adj72, sR2l = wlo_s + WOFF_R2*2 + adj72;

    const int mbid = blockIdx.x - ngather;
    const int nmlp = gridDim.x - ngather;
    const int tpc  = chunk_pts / TILE_PTS;

    for (int c = 0; c < NCHUNKS; c++) {
        if (tid == 0) {
            volatile int* dp = &g_done[c];
            while (*dp < ngather) __nanosleep(256);
        }
        __syncthreads();

        for (int tile = c * tpc + mbid; tile < (c + 1) * tpc; tile += nmlp) {
            const int base = tile * TILE_PTS;

            u32 ah[20], al[20];
            float dxA, dyA, dzA, dxB, dyB, dzB;
            {
                int pt0 = base + rg * 16 + qr;
                int pt1 = pt0 + 8;
                const u32* e0 = g_enc + (size_t)pt0 * LVLS;
                const u32* e1 = g_enc + (size_t)pt1 * LVLS;
#pragma unroll
                for (int kt = 0; kt < 3; kt++) {
                    ah[4*kt+0] = __ldcg(e0 + qm + 8 * kt);
                    ah[4*kt+1] = __ldcg(e1 + qm + 8 * kt);
                    ah[4*kt+2] = __ldcg(e0 + qm + 8 * kt + 4);
                    ah[4*kt+3] = __ldcg(e1 + qm + 8 * kt + 4);
                }
                dxA = __ldg(dirs + pt0 * 3 + 0);
                dyA = __ldg(dirs + pt0 * 3 + 1);
                dzA = __ldg(dirs + pt0 * 3 + 2);
                dxB = __ldg(dirs + pt1 * 3 + 0);
                dyB = __ldg(dirs + pt1 * 3 + 1);
                dzB = __ldg(dirs + pt1 * 3 + 2);
            }

            float acc[8][4];
            run_layer_l0<8, 56>(ah, sL0h, sL0l, bias + BOFF_L0, acc, qm);

            frags_gelu<4>(acc, ah, al);
            run_layer_lds<0, 4, 8, 72, true>(ah, al, sL1h, sL1l,
                                             bias + BOFF_L1, acc, qm);
            frags_gelu<4>(acc, ah, al);
            run_layer_lds<0, 4, 8, 72, true>(ah, al, sL2h, sL2l,
                                             bias + BOFF_L2, acc, qm);
            frags_gelu<4>(acc, ah, al);
            float acc9[9][4];
            run_layer_lds<0, 4, 9, 72, true>(ah, al, sL3h, sL3l,
                                             bias + BOFF_L3, acc9, qm);

            if (qm == 0) {
                int pA = base + rg * 16 + qr;
                out[(size_t)3 * n + pA]     = softplus_f(acc9[0][0]);
                out[(size_t)3 * n + pA + 8] = softplus_f(acc9[0][2]);
            }

            float shA[9], shB[9];
            shA[0] = 0.28209479177387814f;
            shA[1] = -0.48860251190291987f * dyA;
            shA[2] =  0.48860251190291987f * dzA;
            shA[3] = -0.48860251190291987f * dxA;
            shA[4] =  1.0925484305920792f  * dxA * dyA;
            shA[5] = -1.0925484305920792f  * dyA * dzA;
            shA[6] =  0.31539156525252005f * (3.0f * dzA * dzA - 1.0f);
            shA[7] = -1.0925484305920792f  * dxA * dzA;
            shA[8] =  0.5462742152960396f  * (dxA * dxA - dyA * dyA);
            shB[0] = 0.28209479177387814f;
            shB[1] = -0.48860251190291987f * dyB;
            shB[2] =  0.48860251190291987f * dzB;
            shB[3] = -0.48860251190291987f * dxB;
            shB[4] =  1.0925484305920792f  * dxB * dyB;
            shB[5] = -1.0925484305920792f  * dyB * dzB;
            shB[6] =  0.31539156525252005f * (3.0f * dzB * dzB - 1.0f);
            shB[7] = -1.0925484305920792f  * dxB * dzB;
            shB[8] =  0.5462742152960396f  * (dxB * dxB - dyB * dyB);

            frags_gelu<4>(acc9, ah, al);
            {
                float e64A = gelu_exact(acc9[8][0]);
                float e64B = gelu_exact(acc9[8][2]);
                float v0A, v1A, v2A, v3A, v0B, v1B, v2B, v3B;
                if (qm == 0) {
                    v0A = e64A;   v1A = shA[0]; v2A = shA[7]; v3A = shA[8];
                    v0B = e64B;   v1B = shB[0]; v2B = shB[7]; v3B = shB[8];
                } else if (qm == 1) {
                    v0A = shA[1]; v1A = shA[2]; v2A = 0.0f;   v3A = 0.0f;
                    v0B = shB[1]; v1B = shB[2]; v2B = 0.0f;   v3B = 0.0f;
                } else if (qm == 2) {
                    v0A = shA[3]; v1A = shA[4]; v2A = 0.0f;   v3A = 0.0f;
                    v0B = shB[3]; v1B = shB[4]; v2B = 0.0f;   v3B = 0.0f;
                } else {
                    v0A = shA[5]; v1A = shA[6]; v2A = 0.0f;   v3A = 0.0f;
                    v0B = shB[5]; v1B = shB[6]; v2B = 0.0f;   v3B = 0.0f;
                }
                pack_split2(v0A, v1A, ah[16], al[16]);
                pack_split2(v0B, v1B, ah[17], al[17]);
                pack_split2(v2A, v3A, ah[18], al[18]);
                pack_split2(v2B, v3B, ah[19], al[19]);
            }

            run_layer_lds<0, 5, 8, 88, true>(ah, al, sR0h, sR0l,
                                             bias + BOFF_R0, acc, qm);
            frags_gelu<4>(acc, ah, al);
            run_layer_lds<0, 4, 8, 72, true>(ah, al, sR1h, sR1l,
                                             bias + BOFF_R1, acc, qm);
            frags_gelu<4>(acc, ah, al);
            {
                float acc1[1][4];
                run_layer_lds<0, 4, 1, 72, true>(ah, al, sR2h, sR2l,
                                                 bias + BOFF_R2, acc1, qm);
                int pt0 = base + rg * 16 + qr;
                int pt1 = pt0 + 8;
                if (qm == 0) {
                    out[pt0 * 3 + 0] = sigmoid_f(acc1[0][0]);
                    out[pt0 * 3 + 1] = sigmoid_f(acc1[0][1]);
                    out[pt1 * 3 + 0] = sigmoid_f(acc1[0][2]);
                    out[pt1 * 3 + 1] = sigmoid_f(acc1[0][3]);
                } else if (qm == 1) {
                    out[pt0 * 3 + 2] = sigmoid_f(acc1[0][0]);
                    out[pt1 * 3 + 2] = sigmoid_f(acc1[0][2]);
                }
            }
        }
    }
}

extern "C" void kernel_launch(void* const* d_in, const int* in_sizes, int n_in,
                              void* d_out, int out_size)
{
    const float* pts   = (const float*)d_in[0];
    const float* dirs  = (const float*)d_in[1];
    const float* table = (const float*)d_in[2];

    WPtrs prm;
    for (int a = 0; a < 14; a++) prm.w[a] = (const float*)d_in[3 + a];

    int n = in_sizes[0] / 3;

    ResArr res;
    double b = exp((log(2048.0) - log(16.0)) / 23.0);
    for (int l = 0; l < LVLS; l++)
        res.r[l] = (float)floor(16.0 * pow(b, (double)l));

    int dev = 0, sms = 148;
    cudaGetDevice(&dev);
    cudaDeviceGetAttribute(&sms, cudaDevAttrMultiProcessorCount, dev);

    int tpc = (n / NCHUNKS) / TILE_PTS;      // 128
    int ngather = sms - tpc;                 // 24 on 152 SMs
    if (ngather < 8) ngather = 8;

    reset_kernel<<<1, 32>>>();

    cudaFuncSetAttribute(fused_kernel,
                         cudaFuncAttributeMaxDynamicSharedMemorySize,
                         SMEM_BYTES);
    fused_kernel<<<sms, NTHREADS, SMEM_BYTES>>>(
        pts, dirs, table, prm, res, (float*)d_out, n, ngather);
}

// round 15
// speedup vs baseline: 3.4753x; 3.1995x over previous
#include <cuda_runtime.h>
#include <cuda_fp16.h>
#include <math.h>
#include <stdint.h>

// ---------------------------------------------------------------------------
// Round 15: R12 two-kernel split with
//  (1) MLP in fp16: hi-only activations, hi/lo weights, 2-term MMA (-30% MMA)
//  (2) gather x-corner pairing: even-ux corner pairs load as one 16B float4
// K1 gather: 1 thread per (point,level), all SMs (per-SM L1tex-bound).
// K2 MLP: register-chained fp16 tensor pipeline, 512 thr, warp-independent.
// ---------------------------------------------------------------------------

#define LVLS 24
#define TSZ  (1u << 19)
#define P1   2654435761u
#define P2   805459861u

#define NPTS      524288
#define TILE_PTS  256
#define NTHREADS  512

#define WOFF_L0 0              // 64 x 56 (K=48)
#define WOFF_L1 3584           // 64 x 72
#define WOFF_L2 8192           // 64 x 72
#define WOFF_L3 12800          // 72 x 72 (N 65->72)
#define WOFF_R0 17984          // 64 x 88 (K=80, staged shifted by 1)
#define WOFF_R1 23616          // 64 x 72
#define WOFF_R2 28224          //  8 x 72 (N 3->8)

#define BOFF_L0 0
#define BOFF_L1 64
#define BOFF_L2 128
#define BOFF_L3 192
#define BOFF_R0 264
#define BOFF_R1 328
#define BOFF_R2 392

#define SO_WHI  0
#define SO_WLO  57600
#define SO_BIAS 115200
#define SMEM_BYTES (SO_BIAS + 400 * 4)        // 116800

struct ResArr { float r[LVLS]; };
struct WPtrs  { const float* w[14]; };

typedef unsigned short u16;
typedef unsigned int   u32;

// enc scratch: [point][level] packed fp16x2 (feat0 lo, feat1 hi) = 50 MB
__device__ u32 g_enc[(size_t)NPTS * LVLS];

__device__ __forceinline__ float gelu_exact(float x) {
    return 0.5f * x * (1.0f + erff(x * 0.70710678118654752440f));
}
__device__ __forceinline__ float softplus_f(float x) {
    return fmaxf(x, 0.0f) + log1pf(expf(-fabsf(x)));
}
__device__ __forceinline__ float sigmoid_f(float x) {
    return 1.0f / (1.0f + expf(-x));
}

#define MMA_F16(d, a0, a1, a2, a3, b0, b1)                                    \
    asm volatile(                                                             \
        "mma.sync.aligned.m16n8k16.row.col.f32.f16.f16.f32 "                  \
        "{%0,%1,%2,%3}, {%4,%5,%6,%7}, {%8,%9}, {%0,%1,%2,%3};"               \
        : "+f"(d[0]), "+f"(d[1]), "+f"(d[2]), "+f"(d[3])                      \
        : "r"(a0), "r"(a1), "r"(a2), "r"(a3), "r"(b0), "r"(b1))

#define LDSM_X4(r0, r1, r2, r3, addr)                                         \
    asm volatile("ldmatrix.sync.aligned.m8n8.x4.shared.b16 {%0,%1,%2,%3}, [%4];" \
        : "=r"(r0), "=r"(r1), "=r"(r2), "=r"(r3) : "r"(addr))

#define LDSM_X2(r0, r1, addr)                                                 \
    asm volatile("ldmatrix.sync.aligned.m8n8.x2.shared.b16 {%0,%1}, [%2];"    \
        : "=r"(r0), "=r"(r1) : "r"(addr))

// pack two fp32 -> fp16x2 (v0 in low half, v1 in high half)
__device__ __forceinline__ u32 pack_h2(float v0, float v1) {
    u32 h;
    asm("cvt.rn.f16x2.f32 %0, %1, %2;" : "=r"(h) : "f"(v1), "f"(v0));
    return h;
}

template<int KP>
__device__ __forceinline__ u32 lane_adj(int lane) {
    int row8  = lane & 7;
    int which = lane >> 3;
    int n_off = ((which & 2) << 2) + row8;
    int k_off = (which & 1) << 3;
    return (u32)((n_off * KP + k_off) * 2);
}

// 2-term fp16 layer: A (hi-only) x (Bhi + Blo)
template<int KT, int NT, int KP>
__device__ __forceinline__ void run_layer(const u32* __restrict__ ah,
                                          u32 shi, u32 slo,
                                          const float* __restrict__ bias,
                                          float (&acc)[NT][4], int qm)
{
#pragma unroll
    for (int nt = 0; nt < NT; nt++) {
        float b0 = bias[nt * 8 + 2 * qm];
        float b1 = bias[nt * 8 + 2 * qm + 1];
        acc[nt][0] = b0; acc[nt][1] = b1;
        acc[nt][2] = b0; acc[nt][3] = b1;
    }
#pragma unroll
    for (int kt = 0; kt < KT; kt++) {
#pragma unroll
        for (int p = 0; p < NT / 2; p++) {
            u32 off = (u32)((p * 16 * KP + kt * 16) * 2);
            u32 bh0, bh1, bh2, bh3, bl0, bl1, bl2, bl3;
            LDSM_X4(bh0, bh1, bh2, bh3, shi + off);
            LDSM_X4(bl0, bl1, bl2, bl3, slo + off);
            MMA_F16(acc[2*p],   ah[4*kt], ah[4*kt+1], ah[4*kt+2], ah[4*kt+3], bh0, bh1);
            MMA_F16(acc[2*p],   ah[4*kt], ah[4*kt+1], ah[4*kt+2], ah[4*kt+3], bl0, bl1);
            MMA_F16(acc[2*p+1], ah[4*kt], ah[4*kt+1], ah[4*kt+2], ah[4*kt+3], bh2, bh3);
            MMA_F16(acc[2*p+1], ah[4*kt], ah[4*kt+1], ah[4*kt+2], ah[4*kt+3], bl2, bl3);
        }
        if (NT & 1) {
            u32 off = (u32)(((NT - 1) * 8 * KP + kt * 16) * 2);
            u32 bh0, bh1, bl0, bl1;
            LDSM_X2(bh0, bh1, shi + off);
            LDSM_X2(bl0, bl1, slo + off);
            MMA_F16(acc[NT-1], ah[4*kt], ah[4*kt+1], ah[4*kt+2], ah[4*kt+3], bh0, bh1);
            MMA_F16(acc[NT-1], ah[4*kt], ah[4*kt+1], ah[4*kt+2], ah[4*kt+3], bl0, bl1);
        }
    }
}

// D acc -> gelu -> next-layer A-fragments (hi-only fp16)
template<int KTN>
__device__ __forceinline__ void frags_gelu(const float (*acc)[4], u32* ah)
{
#pragma unroll
    for (int kt = 0; kt < KTN; kt++) {
        ah[4*kt+0] = pack_h2(gelu_exact(acc[2*kt][0]),   gelu_exact(acc[2*kt][1]));
        ah[4*kt+1] = pack_h2(gelu_exact(acc[2*kt][2]),   gelu_exact(acc[2*kt][3]));
        ah[4*kt+2] = pack_h2(gelu_exact(acc[2*kt+1][0]), gelu_exact(acc[2*kt+1][1]));
        ah[4*kt+3] = pack_h2(gelu_exact(acc[2*kt+1][2]), gelu_exact(acc[2*kt+1][3]));
    }
}

// ============================ KERNEL 1: gather ============================
__global__ void __launch_bounds__(192, 8)
gather_kernel(const float* __restrict__ pts,
              const float* __restrict__ table,
              ResArr res, int n)
{
    int t = blockIdx.x * 192 + threadIdx.x;
    int p = t / LVLS;
    int l = t - p * LVLS;
    if (p >= n) return;

    float x0 = (pts[p * 3 + 0] + 1.0f) * 0.5f;
    float y0 = (pts[p * 3 + 1] + 1.0f) * 0.5f;
    float z0 = (pts[p * 3 + 2] + 1.0f) * 0.5f;

    float rl = res.r[l];
    float posx = x0 * rl, posy = y0 * rl, posz = z0 * rl;
    float fx = floorf(posx), fy = floorf(posy), fz = floorf(posz);
    float wx = posx - fx, wy = posy - fy, wz = posz - fz;
    unsigned ux = (unsigned)fx, uy = (unsigned)fy, uz = (unsigned)fz;
    unsigned hY[2] = {uy * P1, (uy + 1u) * P1};
    unsigned hZ[2] = {uz * P2, (uz + 1u) * P2};
    float wX[2] = {1.0f - wx, wx};
    float wY[2] = {1.0f - wy, wy};
    float wZ[2] = {1.0f - wz, wz};
    const float2* tb = (const float2*)table + (size_t)l * TSZ;

    float2 f[8];
    if ((ux & 1u) == 0u) {
        // x-corner pairing: idx(bx=1) = idx(bx=0) ^ 1 -> one 16B load per pair
        const float4* tb4 = (const float4*)tb;
#pragma unroll
        for (int by = 0; by < 2; by++) {
#pragma unroll
            for (int bz = 0; bz < 2; bz++) {
                unsigned E = (ux ^ hY[by] ^ hZ[bz]) & (TSZ - 1u);
                float4 q = __ldg(tb4 + (E >> 1));
                float2 e0 = make_float2(q.x, q.y);   // entry (E & ~1)
                float2 e1 = make_float2(q.z, q.w);   // entry (E & ~1) + 1
                bool odd = (E & 1u) != 0u;
                f[(0 << 2) | (by << 1) | bz] = odd ? e1 : e0;
                f[(1 << 2) | (by << 1) | bz] = odd ? e0 : e1;
            }
        }
    } else {
        unsigned hX[2] = {ux, ux + 1u};
#pragma unroll
        for (int c = 0; c < 8; c++) {
            int bx = (c >> 2) & 1, by = (c >> 1) & 1, bz = c & 1;
            unsigned idx = (hX[bx] ^ hY[by] ^ hZ[bz]) & (TSZ - 1u);
            f[c] = __ldg(tb + idx);
        }
    }

    float a0 = 0.0f, a1 = 0.0f;
#pragma unroll
    for (int c = 0; c < 8; c++) {
        int bx = (c >> 2) & 1, by = (c >> 1) & 1, bz = c & 1;
        float wt = wX[bx] * wY[by] * wZ[bz];
        a0 = fmaf(f[c].x, wt, a0);
        a1 = fmaf(f[c].y, wt, a1);
    }
    g_enc[(size_t)p * LVLS + l] = pack_h2(a0, a1);
}

// ============================ KERNEL 2: MLP ===============================
__device__ __forceinline__ void split_h(float v, u16& hi, u16& lo) {
    __half h = __float2half_rn(v);
    float r = v - __half2float(h);
    __half l = __float2half_rn(r);
    hi = __half_as_ushort(h);
    lo = __half_as_ushort(l);
}

__device__ void stage_w(const float* __restrict__ g, u16* hi, u16* lo,
                        int realK, int realN, int K, int NPAD, int KP, int tid)
{
    for (int idx = tid; idx < NPAD * K; idx += NTHREADS) {
        int nn = idx / K, kk = idx % K;
        float v = (kk < realK && nn < realN) ? g[kk * realN + nn] : 0.0f;
        u16 h, l;
        split_h(v, h, l);
        hi[nn * KP + kk] = h;
        lo[nn * KP + kk] = l;
    }
}
__device__ void stage_w_shift(const float* __restrict__ g, u16* hi, u16* lo,
                              int tid)
{
    const int K = 80, KP = 88;
    for (int idx = tid; idx < 64 * K; idx += NTHREADS) {
        int nn = idx / K, kk = idx % K;
        float v = (kk >= 1 && kk <= 73) ? g[(kk - 1) * 64 + nn] : 0.0f;
        u16 h, l;
        split_h(v, h, l);
        hi[nn * KP + kk] = h;
        lo[nn * KP + kk] = l;
    }
}
__device__ void stage_b(const float* __restrict__ g, float* dst,
                        int realN, int NPAD, int tid)
{
    for (int i = tid; i < NPAD; i += NTHREADS)
        dst[i] = (i < realN) ? g[i] : 0.0f;
}

__global__ void __launch_bounds__(NTHREADS, 1)
mlp_kernel(const float* __restrict__ dirs,
           WPtrs prm,
           float* __restrict__ out, int n)
{
    extern __shared__ char smem[];
    u16*   whi  = (u16*)(smem + SO_WHI);
    u16*   wlo  = (u16*)(smem + SO_WLO);
    float* bias = (float*)(smem + SO_BIAS);

    const int tid  = threadIdx.x;
    const int warp = tid >> 5;
    const int lane = tid & 31;
    const int qr = lane >> 2, qm = lane & 3;
    const int rg = warp;

    stage_w(prm.w[0],  whi + WOFF_L0, wlo + WOFF_L0, 48, 64, 48, 64, 56, tid);
    stage_w(prm.w[2],  whi + WOFF_L1, wlo + WOFF_L1, 64, 64, 64, 64, 72, tid);
    stage_w(prm.w[4],  whi + WOFF_L2, wlo + WOFF_L2, 64, 64, 64, 64, 72, tid);
    stage_w(prm.w[6],  whi + WOFF_L3, wlo + WOFF_L3, 64, 65, 64, 72, 72, tid);
    stage_w_shift(prm.w[8], whi + WOFF_R0, wlo + WOFF_R0, tid);
    stage_w(prm.w[10], whi + WOFF_R1, wlo + WOFF_R1, 64, 64, 64, 64, 72, tid);
    stage_w(prm.w[12], whi + WOFF_R2, wlo + WOFF_R2, 64,  3, 64,  8, 72, tid);
    stage_b(prm.w[1],  bias + BOFF_L0, 64, 64, tid);
    stage_b(prm.w[3],  bias + BOFF_L1, 64, 64, tid);
    stage_b(prm.w[5],  bias + BOFF_L2, 64, 64, tid);
    stage_b(prm.w[7],  bias + BOFF_L3, 65, 72, tid);
    stage_b(prm.w[9],  bias + BOFF_R0, 64, 64, tid);
    stage_b(prm.w[11], bias + BOFF_R1, 64, 64, tid);
    stage_b(prm.w[13], bias + BOFF_R2,  3,  8, tid);
    __syncthreads();

    const u32 whi_s = (u32)__cvta_generic_to_shared(whi);
    const u32 wlo_s = (u32)__cvta_generic_to_shared(wlo);
    const u32 adj56 = lane_adj<56>(lane);
    const u32 adj72 = lane_adj<72>(lane);
    const u32 adj88 = lane_adj<88>(lane);
    const u32 sL0h = whi_s + WOFF_L0*2 + adj56, sL0l = wlo_s + WOFF_L0*2 + adj56;
    const u32 sL1h = whi_s + WOFF_L1*2 + adj72, sL1l = wlo_s + WOFF_L1*2 + adj72;
    const u32 sL2h = whi_s + WOFF_L2*2 + adj72, sL2l = wlo_s + WOFF_L2*2 + adj72;
    const u32 sL3h = whi_s + WOFF_L3*2 + adj72, sL3l = wlo_s + WOFF_L3*2 + adj72;
    const u32 sR0h = whi_s + WOFF_R0*2 + adj88, sR0l = wlo_s + WOFF_R0*2 + adj88;
    const u32 sR1h = whi_s + WOFF_R1*2 + adj72, sR1l = wlo_s + WOFF_R1*2 + adj72;
    const u32 sR2h = whi_s + WOFF_R2*2 + adj72, sR2l = wlo_s + WOFF_R2*2 + adj72;

    const int ntiles = n / TILE_PTS;
    int tile = blockIdx.x;
    if (tile >= ntiles) return;

    // prefetch state for current tile: enc A-frags + dirs
    u32 pf[12];
    float pdx0, pdy0, pdz0, pdx1, pdy1, pdz1;

    auto prefetch = [&](int tl) {
        int pt0 = tl * TILE_PTS + rg * 16 + qr;
        int pt1 = pt0 + 8;
        const u32* e0 = g_enc + (size_t)pt0 * LVLS;
        const u32* e1 = g_enc + (size_t)pt1 * LVLS;
#pragma unroll
        for (int kt = 0; kt < 3; kt++) {
            pf[4*kt+0] = __ldg(e0 + qm + 8 * kt);
            pf[4*kt+1] = __ldg(e1 + qm + 8 * kt);
            pf[4*kt+2] = __ldg(e0 + qm + 8 * kt + 4);
            pf[4*kt+3] = __ldg(e1 + qm + 8 * kt + 4);
        }
        pdx0 = __ldg(dirs + pt0 * 3 + 0);
        pdy0 = __ldg(dirs + pt0 * 3 + 1);
        pdz0 = __ldg(dirs + pt0 * 3 + 2);
        pdx1 = __ldg(dirs + pt1 * 3 + 0);
        pdy1 = __ldg(dirs + pt1 * 3 + 1);
        pdz1 = __ldg(dirs + pt1 * 3 + 2);
    };

    prefetch(tile);

    while (true) {
        const int base = tile * TILE_PTS;
        const int next = tile + gridDim.x;
        const bool g = (next < ntiles);

        u32 ah[20];
#pragma unroll
        for (int i = 0; i < 12; i++) ah[i] = pf[i];
        float dxA = pdx0, dyA = pdy0, dzA = pdz0;
        float dxB = pdx1, dyB = pdy1, dzB = pdz1;

        if (g) prefetch(next);

        float acc[8][4];
        run_layer<3, 8, 56>(ah, sL0h, sL0l, bias + BOFF_L0, acc, qm);

        frags_gelu<4>(acc, ah);
        run_layer<4, 8, 72>(ah, sL1h, sL1l, bias + BOFF_L1, acc, qm);
        frags_gelu<4>(acc, ah);
        run_layer<4, 8, 72>(ah, sL2h, sL2l, bias + BOFF_L2, acc, qm);
        frags_gelu<4>(acc, ah);
        float acc9[9][4];
        run_layer<4, 9, 72>(ah, sL3h, sL3l, bias + BOFF_L3, acc9, qm);

        // density out
        if (qm == 0) {
            int pA = base + rg * 16 + qr;
            out[(size_t)3 * n + pA]     = softplus_f(acc9[0][0]);
            out[(size_t)3 * n + pA + 8] = softplus_f(acc9[0][2]);
        }
        // SH
        float shA[9], shB[9];
        shA[0] = 0.28209479177387814f;
        shA[1] = -0.48860251190291987f * dyA;
        shA[2] =  0.48860251190291987f * dzA;
        shA[3] = -0.48860251190291987f * dxA;
        shA[4] =  1.0925484305920792f  * dxA * dyA;
        shA[5] = -1.0925484305920792f  * dyA * dzA;
        shA[6] =  0.31539156525252005f * (3.0f * dzA * dzA - 1.0f);
        shA[7] = -1.0925484305920792f  * dxA * dzA;
        shA[8] =  0.5462742152960396f  * (dxA * dxA - dyA * dyA);
        shB[0] = 0.28209479177387814f;
        shB[1] = -0.48860251190291987f * dyB;
        shB[2] =  0.48860251190291987f * dzB;
        shB[3] = -0.48860251190291987f * dxB;
        shB[4] =  1.0925484305920792f  * dxB * dyB;
        shB[5] = -1.0925484305920792f  * dyB * dzB;
        shB[6] =  0.31539156525252005f * (3.0f * dzB * dzB - 1.0f);
        shB[7] = -1.0925484305920792f  * dxB * dzB;
        shB[8] =  0.5462742152960396f  * (dxB * dxB - dyB * dyB);

        // R0 A-frags: cols 0..63 gelu(fad), k-tile 4 = col64 + SH
        frags_gelu<4>(acc9, ah);
        {
            float e64A = gelu_exact(acc9[8][0]);
            float e64B = gelu_exact(acc9[8][2]);
            float v0A, v1A, v2A, v3A, v0B, v1B, v2B, v3B;
            if (qm == 0) {
                v0A = e64A;   v1A = shA[0]; v2A = shA[7]; v3A = shA[8];
                v0B = e64B;   v1B = shB[0]; v2B = shB[7]; v3B = shB[8];
            } else if (qm == 1) {
                v0A = shA[1]; v1A = shA[2]; v2A = 0.0f;   v3A = 0.0f;
                v0B = shB[1]; v1B = shB[2]; v2B = 0.0f;   v3B = 0.0f;
            } else if (qm == 2) {
                v0A = shA[3]; v1A = shA[4]; v2A = 0.0f;   v3A = 0.0f;
                v0B = shB[3]; v1B = shB[4]; v2B = 0.0f;   v3B = 0.0f;
            } else {
                v0A = shA[5]; v1A = shA[6]; v2A = 0.0f;   v3A = 0.0f;
                v0B = shB[5]; v1B = shB[6]; v2B = 0.0f;   v3B = 0.0f;
            }
            ah[16] = pack_h2(v0A, v1A);
            ah[17] = pack_h2(v0B, v1B);
            ah[18] = pack_h2(v2A, v3A);
            ah[19] = pack_h2(v2B, v3B);
        }

        run_layer<5, 8, 88>(ah, sR0h, sR0l, bias + BOFF_R0, acc, qm);
        frags_gelu<4>(acc, ah);
        run_layer<4, 8, 72>(ah, sR1h, sR1l, bias + BOFF_R1, acc, qm);
        frags_gelu<4>(acc, ah);
        {
            float acc1[1][4];
            run_layer<4, 1, 72>(ah, sR2h, sR2l, bias + BOFF_R2, acc1, qm);
            int pt0 = base + rg * 16 + qr;
            int pt1 = pt0 + 8;
            if (qm == 0) {
                out[pt0 * 3 + 0] = sigmoid_f(acc1[0][0]);
                out[pt0 * 3 + 1] = sigmoid_f(acc1[0][1]);
                out[pt1 * 3 + 0] = sigmoid_f(acc1[0][2]);
                out[pt1 * 3 + 1] = sigmoid_f(acc1[0][3]);
            } else if (qm == 1) {
                out[pt0 * 3 + 2] = sigmoid_f(acc1[0][0]);
                out[pt1 * 3 + 2] = sigmoid_f(acc1[0][2]);
            }
        }

        if (!g) break;
        tile = next;
    }
}

extern "C" void kernel_launch(void* const* d_in, const int* in_sizes, int n_in,
                              void* d_out, int out_size)
{
    const float* pts   = (const float*)d_in[0];
    const float* dirs  = (const float*)d_in[1];
    const float* table = (const float*)d_in[2];

    WPtrs prm;
    for (int a = 0; a < 14; a++) prm.w[a] = (const float*)d_in[3 + a];

    int n = in_sizes[0] / 3;

    ResArr res;
    double b = exp((log(2048.0) - log(16.0)) / 23.0);
    for (int l = 0; l < LVLS; l++)
        res.r[l] = (float)floor(16.0 * pow(b, (double)l));

    // Kernel 1: gather
    {
        int blocks = (n * LVLS + 191) / 192;
        gather_kernel<<<blocks, 192>>>(pts, table, res, n);
    }

    // Kernel 2: MLP
    {
        cudaFuncSetAttribute(mlp_kernel,
                             cudaFuncAttributeMaxDynamicSharedMemorySize,
                             SMEM_BYTES);
        int dev = 0, sms = 148;
        cudaGetDevice(&dev);
        cudaDeviceGetAttribute(&sms, cudaDevAttrMultiProcessorCount, dev);
        int ntiles = n / TILE_PTS;
        int blocks = (sms < ntiles) ? sms : ntiles;
        mlp_kernel<<<blocks, NTHREADS, SMEM_BYTES>>>(
            dirs, prm, (float*)d_out, n);
    }
}

// round 16
// speedup vs baseline: 6.0051x; 1.7279x over previous
#include <cuda_runtime.h>
#include <cuda_fp16.h>
#include <math.h>
#include <stdint.h>

// ---------------------------------------------------------------------------
// Round 16: R15 +
//  (1) GELU via tanh.approx.f32 (7 instr, branch-free) in the MLP epilogues
//  (2) weights hi-only fp16 -> 1-term MMA (half the MMA + LDSM)
// K1 gather: 1 thread/(point,level), x-corner pairing, all SMs.
// K2 MLP: register-chained fp16 tensor pipeline, 512 thr, warp-independent.
// ---------------------------------------------------------------------------

#define LVLS 24
#define TSZ  (1u << 19)
#define P1   2654435761u
#define P2   805459861u

#define NPTS      524288
#define TILE_PTS  256
#define NTHREADS  512

#define WOFF_L0 0              // 64 x 56 (K=48)
#define WOFF_L1 3584           // 64 x 72
#define WOFF_L2 8192           // 64 x 72
#define WOFF_L3 12800          // 72 x 72 (N 65->72)
#define WOFF_R0 17984          // 64 x 88 (K=80, staged shifted by 1)
#define WOFF_R1 23616          // 64 x 72
#define WOFF_R2 28224          //  8 x 72 (N 3->8)

#define BOFF_L0 0
#define BOFF_L1 64
#define BOFF_L2 128
#define BOFF_L3 192
#define BOFF_R0 264
#define BOFF_R1 328
#define BOFF_R2 392

#define SO_WHI  0
#define SO_BIAS 57600
#define SMEM_BYTES (SO_BIAS + 400 * 4)        // 59200

struct ResArr { float r[LVLS]; };
struct WPtrs  { const float* w[14]; };

typedef unsigned short u16;
typedef unsigned int   u32;

// enc scratch: [point][level] packed fp16x2
__device__ u32 g_enc[(size_t)NPTS * LVLS];

__device__ __forceinline__ float gelu_fast(float x) {
    float x2 = x * x;
    float inner = fmaf(0.044715f * x2, x, x) * 0.7978845608028654f;
    float t;
    asm("tanh.approx.f32 %0, %1;" : "=f"(t) : "f"(inner));
    float hx = 0.5f * x;
    return fmaf(hx, t, hx);
}
__device__ __forceinline__ float softplus_f(float x) {
    return fmaxf(x, 0.0f) + log1pf(expf(-fabsf(x)));
}
__device__ __forceinline__ float sigmoid_f(float x) {
    return 1.0f / (1.0f + expf(-x));
}

#define MMA_F16(d, a0, a1, a2, a3, b0, b1)                                    \
    asm volatile(                                                             \
        "mma.sync.aligned.m16n8k16.row.col.f32.f16.f16.f32 "                  \
        "{%0,%1,%2,%3}, {%4,%5,%6,%7}, {%8,%9}, {%0,%1,%2,%3};"               \
        : "+f"(d[0]), "+f"(d[1]), "+f"(d[2]), "+f"(d[3])                      \
        : "r"(a0), "r"(a1), "r"(a2), "r"(a3), "r"(b0), "r"(b1))

#define LDSM_X4(r0, r1, r2, r3, addr)                                         \
    asm volatile("ldmatrix.sync.aligned.m8n8.x4.shared.b16 {%0,%1,%2,%3}, [%4];" \
        : "=r"(r0), "=r"(r1), "=r"(r2), "=r"(r3) : "r"(addr))

#define LDSM_X2(r0, r1, addr)                                                 \
    asm volatile("ldmatrix.sync.aligned.m8n8.x2.shared.b16 {%0,%1}, [%2];"    \
        : "=r"(r0), "=r"(r1) : "r"(addr))

__device__ __forceinline__ u32 pack_h2(float v0, float v1) {
    u32 h;
    asm("cvt.rn.f16x2.f32 %0, %1, %2;" : "=r"(h) : "f"(v1), "f"(v0));
    return h;
}

template<int KP>
__device__ __forceinline__ u32 lane_adj(int lane) {
    int row8  = lane & 7;
    int which = lane >> 3;
    int n_off = ((which & 2) << 2) + row8;
    int k_off = (which & 1) << 3;
    return (u32)((n_off * KP + k_off) * 2);
}

// 1-term fp16 layer (weights hi-only)
template<int KT, int NT, int KP>
__device__ __forceinline__ void run_layer(const u32* __restrict__ ah,
                                          u32 shi,
                                          const float* __restrict__ bias,
                                          float (&acc)[NT][4], int qm)
{
#pragma unroll
    for (int nt = 0; nt < NT; nt++) {
        float b0 = bias[nt * 8 + 2 * qm];
        float b1 = bias[nt * 8 + 2 * qm + 1];
        acc[nt][0] = b0; acc[nt][1] = b1;
        acc[nt][2] = b0; acc[nt][3] = b1;
    }
#pragma unroll
    for (int kt = 0; kt < KT; kt++) {
#pragma unroll
        for (int p = 0; p < NT / 2; p++) {
            u32 off = (u32)((p * 16 * KP + kt * 16) * 2);
            u32 bh0, bh1, bh2, bh3;
            LDSM_X4(bh0, bh1, bh2, bh3, shi + off);
            MMA_F16(acc[2*p],   ah[4*kt], ah[4*kt+1], ah[4*kt+2], ah[4*kt+3], bh0, bh1);
            MMA_F16(acc[2*p+1], ah[4*kt], ah[4*kt+1], ah[4*kt+2], ah[4*kt+3], bh2, bh3);
        }
        if (NT & 1) {
            u32 off = (u32)(((NT - 1) * 8 * KP + kt * 16) * 2);
            u32 bh0, bh1;
            LDSM_X2(bh0, bh1, shi + off);
            MMA_F16(acc[NT-1], ah[4*kt], ah[4*kt+1], ah[4*kt+2], ah[4*kt+3], bh0, bh1);
        }
    }
}

template<int KTN>
__device__ __forceinline__ void frags_gelu(const float (*acc)[4], u32* ah)
{
#pragma unroll
    for (int kt = 0; kt < KTN; kt++) {
        ah[4*kt+0] = pack_h2(gelu_fast(acc[2*kt][0]),   gelu_fast(acc[2*kt][1]));
        ah[4*kt+1] = pack_h2(gelu_fast(acc[2*kt][2]),   gelu_fast(acc[2*kt][3]));
        ah[4*kt+2] = pack_h2(gelu_fast(acc[2*kt+1][0]), gelu_fast(acc[2*kt+1][1]));
        ah[4*kt+3] = pack_h2(gelu_fast(acc[2*kt+1][2]), gelu_fast(acc[2*kt+1][3]));
    }
}

// ============================ KERNEL 1: gather ============================
__global__ void __launch_bounds__(192, 8)
gather_kernel(const float* __restrict__ pts,
              const float* __restrict__ table,
              ResArr res, int n)
{
    int t = blockIdx.x * 192 + threadIdx.x;
    int p = t / LVLS;
    int l = t - p * LVLS;
    if (p >= n) return;

    float x0 = (pts[p * 3 + 0] + 1.0f) * 0.5f;
    float y0 = (pts[p * 3 + 1] + 1.0f) * 0.5f;
    float z0 = (pts[p * 3 + 2] + 1.0f) * 0.5f;

    float rl = res.r[l];
    float posx = x0 * rl, posy = y0 * rl, posz = z0 * rl;
    float fx = floorf(posx), fy = floorf(posy), fz = floorf(posz);
    float wx = posx - fx, wy = posy - fy, wz = posz - fz;
    unsigned ux = (unsigned)fx, uy = (unsigned)fy, uz = (unsigned)fz;
    unsigned hY[2] = {uy * P1, (uy + 1u) * P1};
    unsigned hZ[2] = {uz * P2, (uz + 1u) * P2};
    float wX[2] = {1.0f - wx, wx};
    float wY[2] = {1.0f - wy, wy};
    float wZ[2] = {1.0f - wz, wz};
    const float2* tb = (const float2*)table + (size_t)l * TSZ;

    float2 f[8];
    if ((ux & 1u) == 0u) {
        const float4* tb4 = (const float4*)tb;
#pragma unroll
        for (int by = 0; by < 2; by++) {
#pragma unroll
            for (int bz = 0; bz < 2; bz++) {
                unsigned E = (ux ^ hY[by] ^ hZ[bz]) & (TSZ - 1u);
                float4 q = __ldg(tb4 + (E >> 1));
                float2 e0 = make_float2(q.x, q.y);
                float2 e1 = make_float2(q.z, q.w);
                bool odd = (E & 1u) != 0u;
                f[(0 << 2) | (by << 1) | bz] = odd ? e1 : e0;
                f[(1 << 2) | (by << 1) | bz] = odd ? e0 : e1;
            }
        }
    } else {
        unsigned hX[2] = {ux, ux + 1u};
#pragma unroll
        for (int c = 0; c < 8; c++) {
            int bx = (c >> 2) & 1, by = (c >> 1) & 1, bz = c & 1;
            unsigned idx = (hX[bx] ^ hY[by] ^ hZ[bz]) & (TSZ - 1u);
            f[c] = __ldg(tb + idx);
        }
    }

    float a0 = 0.0f, a1 = 0.0f;
#pragma unroll
    for (int c = 0; c < 8; c++) {
        int bx = (c >> 2) & 1, by = (c >> 1) & 1, bz = c & 1;
        float wt = wX[bx] * wY[by] * wZ[bz];
        a0 = fmaf(f[c].x, wt, a0);
        a1 = fmaf(f[c].y, wt, a1);
    }
    g_enc[(size_t)p * LVLS + l] = pack_h2(a0, a1);
}

// ============================ KERNEL 2: MLP ===============================
__device__ void stage_w(const float* __restrict__ g, u16* hi,
                        int realK, int realN, int K, int NPAD, int KP, int tid)
{
    for (int idx = tid; idx < NPAD * K; idx += NTHREADS) {
        int nn = idx / K, kk = idx % K;
        float v = (kk < realK && nn < realN) ? g[kk * realN + nn] : 0.0f;
        hi[nn * KP + kk] = __half_as_ushort(__float2half_rn(v));
    }
}
__device__ void stage_w_shift(const float* __restrict__ g, u16* hi, int tid)
{
    const int K = 80, KP = 88;
    for (int idx = tid; idx < 64 * K; idx += NTHREADS) {
        int nn = idx / K, kk = idx % K;
        float v = (kk >= 1 && kk <= 73) ? g[(kk - 1) * 64 + nn] : 0.0f;
        hi[nn * KP + kk] = __half_as_ushort(__float2half_rn(v));
    }
}
__device__ void stage_b(const float* __restrict__ g, float* dst,
                        int realN, int NPAD, int tid)
{
    for (int i = tid; i < NPAD; i += NTHREADS)
        dst[i] = (i < realN) ? g[i] : 0.0f;
}

__global__ void __launch_bounds__(NTHREADS, 1)
mlp_kernel(const float* __restrict__ dirs,
           WPtrs prm,
           float* __restrict__ out, int n)
{
    extern __shared__ char smem[];
    u16*   whi  = (u16*)(smem + SO_WHI);
    float* bias = (float*)(smem + SO_BIAS);

    const int tid  = threadIdx.x;
    const int warp = tid >> 5;
    const int lane = tid & 31;
    const int qr = lane >> 2, qm = lane & 3;
    const int rg = warp;

    stage_w(prm.w[0],  whi + WOFF_L0, 48, 64, 48, 64, 56, tid);
    stage_w(prm.w[2],  whi + WOFF_L1, 64, 64, 64, 64, 72, tid);
    stage_w(prm.w[4],  whi + WOFF_L2, 64, 64, 64, 64, 72, tid);
    stage_w(prm.w[6],  whi + WOFF_L3, 64, 65, 64, 72, 72, tid);
    stage_w_shift(prm.w[8], whi + WOFF_R0, tid);
    stage_w(prm.w[10], whi + WOFF_R1, 64, 64, 64, 64, 72, tid);
    stage_w(prm.w[12], whi + WOFF_R2, 64,  3, 64,  8, 72, tid);
    stage_b(prm.w[1],  bias + BOFF_L0, 64, 64, tid);
    stage_b(prm.w[3],  bias + BOFF_L1, 64, 64, tid);
    stage_b(prm.w[5],  bias + BOFF_L2, 64, 64, tid);
    stage_b(prm.w[7],  bias + BOFF_L3, 65, 72, tid);
    stage_b(prm.w[9],  bias + BOFF_R0, 64, 64, tid);
    stage_b(prm.w[11], bias + BOFF_R1, 64, 64, tid);
    stage_b(prm.w[13], bias + BOFF_R2,  3,  8, tid);
    __syncthreads();

    const u32 whi_s = (u32)__cvta_generic_to_shared(whi);
    const u32 adj56 = lane_adj<56>(lane);
    const u32 adj72 = lane_adj<72>(lane);
    const u32 adj88 = lane_adj<88>(lane);
    const u32 sL0h = whi_s + WOFF_L0*2 + adj56;
    const u32 sL1h = whi_s + WOFF_L1*2 + adj72;
    const u32 sL2h = whi_s + WOFF_L2*2 + adj72;
    const u32 sL3h = whi_s + WOFF_L3*2 + adj72;
    const u32 sR0h = whi_s + WOFF_R0*2 + adj88;
    const u32 sR1h = whi_s + WOFF_R1*2 + adj72;
    const u32 sR2h = whi_s + WOFF_R2*2 + adj72;

    const int ntiles = n / TILE_PTS;
    int tile = blockIdx.x;
    if (tile >= ntiles) return;

    u32 pf[12];
    float pdx0, pdy0, pdz0, pdx1, pdy1, pdz1;

    auto prefetch = [&](int tl) {
        int pt0 = tl * TILE_PTS + rg * 16 + qr;
        int pt1 = pt0 + 8;
        const u32* e0 = g_enc + (size_t)pt0 * LVLS;
        const u32* e1 = g_enc + (size_t)pt1 * LVLS;
#pragma unroll
        for (int kt = 0; kt < 3; kt++) {
            pf[4*kt+0] = __ldg(e0 + qm + 8 * kt);
            pf[4*kt+1] = __ldg(e1 + qm + 8 * kt);
            pf[4*kt+2] = __ldg(e0 + qm + 8 * kt + 4);
            pf[4*kt+3] = __ldg(e1 + qm + 8 * kt + 4);
        }
        pdx0 = __ldg(dirs + pt0 * 3 + 0);
        pdy0 = __ldg(dirs + pt0 * 3 + 1);
        pdz0 = __ldg(dirs + pt0 * 3 + 2);
        pdx1 = __ldg(dirs + pt1 * 3 + 0);
        pdy1 = __ldg(dirs + pt1 * 3 + 1);
        pdz1 = __ldg(dirs + pt1 * 3 + 2);
    };

    prefetch(tile);

    while (true) {
        const int base = tile * TILE_PTS;
        const int next = tile + gridDim.x;
        const bool g = (next < ntiles);

        u32 ah[20];
#pragma unroll
        for (int i = 0; i < 12; i++) ah[i] = pf[i];
        float dxA = pdx0, dyA = pdy0, dzA = pdz0;
        float dxB = pdx1, dyB = pdy1, dzB = pdz1;

        if (g) prefetch(next);

        float acc[8][4];
        run_layer<3, 8, 56>(ah, sL0h, bias + BOFF_L0, acc, qm);

        frags_gelu<4>(acc, ah);
        run_layer<4, 8, 72>(ah, sL1h, bias + BOFF_L1, acc, qm);
        frags_gelu<4>(acc, ah);
        run_layer<4, 8, 72>(ah, sL2h, bias + BOFF_L2, acc, qm);
        frags_gelu<4>(acc, ah);
        float acc9[9][4];
        run_layer<4, 9, 72>(ah, sL3h, bias + BOFF_L3, acc9, qm);

        if (qm == 0) {
            int pA = base + rg * 16 + qr;
            out[(size_t)3 * n + pA]     = softplus_f(acc9[0][0]);
            out[(size_t)3 * n + pA + 8] = softplus_f(acc9[0][2]);
        }

        float shA[9], shB[9];
        shA[0] = 0.28209479177387814f;
        shA[1] = -0.48860251190291987f * dyA;
        shA[2] =  0.48860251190291987f * dzA;
        shA[3] = -0.48860251190291987f * dxA;
        shA[4] =  1.0925484305920792f  * dxA * dyA;
        shA[5] = -1.0925484305920792f  * dyA * dzA;
        shA[6] =  0.31539156525252005f * (3.0f * dzA * dzA - 1.0f);
        shA[7] = -1.0925484305920792f  * dxA * dzA;
        shA[8] =  0.5462742152960396f  * (dxA * dxA - dyA * dyA);
        shB[0] = 0.28209479177387814f;
        shB[1] = -0.48860251190291987f * dyB;
        shB[2] =  0.48860251190291987f * dzB;
        shB[3] = -0.48860251190291987f * dxB;
        shB[4] =  1.0925484305920792f  * dxB * dyB;
        shB[5] = -1.0925484305920792f  * dyB * dzB;
        shB[6] =  0.31539156525252005f * (3.0f * dzB * dzB - 1.0f);
        shB[7] = -1.0925484305920792f  * dxB * dzB;
        shB[8] =  0.5462742152960396f  * (dxB * dxB - dyB * dyB);

        frags_gelu<4>(acc9, ah);
        {
            float e64A = gelu_fast(acc9[8][0]);
            float e64B = gelu_fast(acc9[8][2]);
            float v0A, v1A, v2A, v3A, v0B, v1B, v2B, v3B;
            if (qm == 0) {
                v0A = e64A;   v1A = shA[0]; v2A = shA[7]; v3A = shA[8];
                v0B = e64B;   v1B = shB[0]; v2B = shB[7]; v3B = shB[8];
            } else if (qm == 1) {
                v0A = shA[1]; v1A = shA[2]; v2A = 0.0f;   v3A = 0.0f;
                v0B = shB[1]; v1B = shB[2]; v2B = 0.0f;   v3B = 0.0f;
            } else if (qm == 2) {
                v0A = shA[3]; v1A = shA[4]; v2A = 0.0f;   v3A = 0.0f;
                v0B = shB[3]; v1B = shB[4]; v2B = 0.0f;   v3B = 0.0f;
            } else {
                v0A = shA[5]; v1A = shA[6]; v2A = 0.0f;   v3A = 0.0f;
                v0B = shB[5]; v1B = shB[6]; v2B = 0.0f;   v3B = 0.0f;
            }
            ah[16] = pack_h2(v0A, v1A);
            ah[17] = pack_h2(v0B, v1B);
            ah[18] = pack_h2(v2A, v3A);
            ah[19] = pack_h2(v2B, v3B);
        }

        run_layer<5, 8, 88>(ah, sR0h, bias + BOFF_R0, acc, qm);
        frags_gelu<4>(acc, ah);
        run_layer<4, 8, 72>(ah, sR1h, bias + BOFF_R1, acc, qm);
        frags_gelu<4>(acc, ah);
        {
            float acc1[1][4];
            run_layer<4, 1, 72>(ah, sR2h, bias + BOFF_R2, acc1, qm);
            int pt0 = base + rg * 16 + qr;
            int pt1 = pt0 + 8;
            if (qm == 0) {
                out[pt0 * 3 + 0] = sigmoid_f(acc1[0][0]);
                out[pt0 * 3 + 1] = sigmoid_f(acc1[0][1]);
                out[pt1 * 3 + 0] = sigmoid_f(acc1[0][2]);
                out[pt1 * 3 + 1] = sigmoid_f(acc1[0][3]);
            } else if (qm == 1) {
                out[pt0 * 3 + 2] = sigmoid_f(acc1[0][0]);
                out[pt1 * 3 + 2] = sigmoid_f(acc1[0][2]);
            }
        }

        if (!g) break;
        tile = next;
    }
}

extern "C" void kernel_launch(void* const* d_in, const int* in_sizes, int n_in,
                              void* d_out, int out_size)
{
    const float* pts   = (const float*)d_in[0];
    const float* dirs  = (const float*)d_in[1];
    const float* table = (const float*)d_in[2];

    WPtrs prm;
    for (int a = 0; a < 14; a++) prm.w[a] = (const float*)d_in[3 + a];

    int n = in_sizes[0] / 3;

    ResArr res;
    double b = exp((log(2048.0) - log(16.0)) / 23.0);
    for (int l = 0; l < LVLS; l++)
        res.r[l] = (float)floor(16.0 * pow(b, (double)l));

    // Kernel 1: gather
    {
        int blocks = (n * LVLS + 191) / 192;
        gather_kernel<<<blocks, 192>>>(pts, table, res, n);
    }

    // Kernel 2: MLP
    {
        cudaFuncSetAttribute(mlp_kernel,
                             cudaFuncAttributeMaxDynamicSharedMemorySize,
                             SMEM_BYTES);
        int dev = 0, sms = 148;
        cudaGetDevice(&dev);
        cudaDeviceGetAttribute(&sms, cudaDevAttrMultiProcessorCount, dev);
        int ntiles = n / TILE_PTS;
        int blocks = (sms < ntiles) ? sms : ntiles;
        mlp_kernel<<<blocks, NTHREADS, SMEM_BYTES>>>(
            dirs, prm, (float*)d_out, n);
    }
}